// round 5
// baseline (speedup 1.0000x reference)
#include <cuda_runtime.h>
#include <math_constants.h>

// Problem constants
#define B_      256
#define N_      16
#define M_      128
#define V_      64
#define H_      256
#define K_      8
#define NP1_    17      // N + 1
#define KO_     136     // K * (N+1)
#define TYPES_  12
#define NCOMBO  180     // 15 spans x 12 types
#define GRID    148     // <= SM count -> all blocks co-resident
#define NT      544     // 136 outputs x 4 sub-chunks

// Output layout: new_d [B,M,V] floats, then new_v [B,40,3,V] zeros
#define OUT_D_ELEMS ((size_t)B_ * M_ * V_)
#define OUT_V_PER_B (40 * 3 * V_)   // 7680 floats per batch

// Scratch: partial dots [combo][quad][o] (double), + barrier state.
__device__ double       g_part[(size_t)NCOMBO * 4 * KO_];
__device__ int          g_arrive;
__device__ volatile int g_go;
__device__ int          g_done;

__global__ __launch_bounds__(NT, 1)
void persistent_kernel(
    const float* __restrict__ decodings,     // [B,N,M,V]
    const int*   __restrict__ target_types,  // [B]
    const int*   __restrict__ spans,         // [B]
    const float* __restrict__ te_table,      // [21,H]
    const float* __restrict__ W_sem,         // [15,12,H,KO]
    const float* __restrict__ b_sem,         // [15,12,KO]
    const float* __restrict__ gumbel,        // [B,K,NP1]
    float*       __restrict__ out)
{
    __shared__ unsigned char s_flag[NCOMBO];
    __shared__ float         s_te[64];
    __shared__ double        s_part[NT];
    __shared__ int           s_sel[K_];
    __shared__ int           s_red[16];
    __shared__ int           s_olen;

    const int tid  = threadIdx.x;
    const int bid  = blockIdx.x;
    const int w    = tid >> 5;
    const int lane = tid & 31;

    // ---- Phase 0: new_v zero fill (grid-strided, overlaps phase 1 loads) ----
    {
        float4* __restrict__ dv = (float4*)(out + OUT_D_ELEMS);
        const int total4 = (B_ * OUT_V_PER_B) / 4;     // 491,520
        const float4 z = make_float4(0.f, 0.f, 0.f, 0.f);
        for (int i = bid * NT + tid; i < total4; i += GRID * NT)
            dv[i] = z;
    }

    // ---- build combo-presence flags in SMEM (1 KB of control reads) ----
    for (int i = tid; i < NCOMBO; i += NT) s_flag[i] = 0;
    __syncthreads();
    if (tid < B_) {
        const int t = target_types[tid];
        const int s = spans[tid];
        if (t != 20) s_flag[(s - 2) * TYPES_ + (t - 9)] = 1;
    }
    __syncthreads();

    // ---- Phase 1: deduped GEMV units (combo x H-quadrant) ----
    // Thread = (output o, 16-h sub-chunk): 16 independent loads per unit.
    const int o   = tid % KO_;
    const int sub = tid / KO_;
    for (int u = bid; u < NCOMBO * 4; u += GRID) {
        const int combo = u >> 2;
        const int quad  = u & 3;
        if (!s_flag[combo]) continue;

        const int tt = 9 + combo % TYPES_;
        if (tid < 64) s_te[tid] = te_table[(size_t)tt * H_ + quad * 64 + tid];
        __syncthreads();

        const float* __restrict__ wp =
            W_sem + ((size_t)combo * H_ + (size_t)(quad * 64 + sub * 16)) * KO_ + o;
        const float* __restrict__ tp = s_te + sub * 16;

        float p[16];
        #pragma unroll
        for (int j = 0; j < 16; j++)
            p[j] = tp[j] * wp[(size_t)j * KO_];
        double s = 0.0;
        #pragma unroll
        for (int j = 0; j < 16; j += 2)
            s += (double)p[j] + (double)p[j + 1];
        s_part[tid] = s;
        __syncthreads();

        if (tid < KO_) {
            g_part[(size_t)(combo * 4 + quad) * KO_ + tid] =
                (s_part[tid] + s_part[tid + KO_]) +
                (s_part[tid + 2 * KO_] + s_part[tid + 3 * KO_]);
        }
        __syncthreads();   // s_te reused next unit
    }

    // ---- in-grid barrier (all GRID blocks co-resident) ----
    __threadfence();
    __syncthreads();
    if (tid == 0) {
        const int old = atomicAdd(&g_arrive, 1);
        if (old == GRID - 1) {
            g_arrive = 0;
            __threadfence();
            g_go = 1;
        } else {
            while (g_go == 0) __nanosleep(64);
        }
    }
    __syncthreads();

    // ---- Phase 2: per-batch selection + template application ----
    const int c4    = tid & 15;         // float4 column (V=64 -> 16 float4/row)
    const int rbase = (tid >> 4) & 31;  // base row 0..31 (tid < 512)

    for (int b = bid; b < B_; b += GRID) {
        const int tt = target_types[b];
        const int sp = spans[b];

        if (tt == 20) {
            if (tid < K_) s_sel[tid] = (tid == 0) ? 1 : 0;
        } else if (w < K_) {
            float val = -CUDART_INF_F;
            if (lane < NP1_ && lane <= sp) {
                const int combo = (sp - 2) * TYPES_ + (tt - 9);
                const size_t base = (size_t)combo * 4 * KO_;
                const int oo = w * NP1_ + lane;
                const double sl = (g_part[base + oo] + g_part[base + KO_ + oo])
                                + (g_part[base + 2 * KO_ + oo] + g_part[base + 3 * KO_ + oo]);
                val = (float)sl + __ldg(&b_sem[(size_t)combo * KO_ + oo])
                    + __ldg(&gumbel[((size_t)b * K_ + w) * NP1_ + lane]);
            }
            float bv = val;
            int   bn = lane;
            #pragma unroll
            for (int off = 16; off; off >>= 1) {
                float ov = __shfl_down_sync(0xffffffffu, bv, off);
                int   on = __shfl_down_sync(0xffffffffu, bn, off);
                if (ov > bv || (ov == bv && on < bn)) { bv = ov; bn = on; }
            }
            if (lane == 0) s_sel[w] = bn;
        }
        __syncthreads();

        // fused speculative copy + olen (usually one iteration)
        int idx = 0;
        for (int k = 0; k < K_; k++) {
            if (idx >= M_) break;
            const int n = s_sel[k];
            if (n == 0) continue;

            if (tid < 512) {
                const float4* __restrict__ tile4 =
                    (const float4*)(decodings + ((size_t)b * N_ + (size_t)(n - 1)) * (M_ * V_));
                float4* __restrict__ out4 =
                    (float4*)(out + ((size_t)b * M_ + idx) * V_);

                float4 v[4];
                #pragma unroll
                for (int j = 0; j < 4; j++)
                    v[j] = tile4[(rbase + 32 * j) * 16 + c4];

                int local = 0;
                #pragma unroll
                for (int j = 0; j < 4; j++) {
                    const int row = rbase + 32 * j;
                    if (idx + row < M_)
                        out4[row * 16 + c4] = v[j];
                    // row non-pad iff max over v>0 of d[row][v] > d[row][0]
                    float m = (c4 == 0) ? fmaxf(fmaxf(v[j].y, v[j].z), v[j].w)
                                        : fmaxf(fmaxf(v[j].x, v[j].y), fmaxf(v[j].z, v[j].w));
                    #pragma unroll
                    for (int off = 1; off < 16; off <<= 1)
                        m = fmaxf(m, __shfl_xor_sync(0xffffffffu, m, off));
                    const float d0 = __shfl_sync(0xffffffffu, v[j].x, lane & 16);
                    if (m > d0) local = row + 1;
                }
                #pragma unroll
                for (int off = 16; off; off >>= 1)
                    local = max(local, __shfl_down_sync(0xffffffffu, local, off));
                if (lane == 0) s_red[w] = local;
            }
            __syncthreads();
            if (tid == 0) {
                int mx = 0;
                #pragma unroll
                for (int i = 0; i < 16; i++) mx = max(mx, s_red[i]);
                s_olen = mx;
            }
            __syncthreads();
            idx += min(s_olen, M_ - idx);
        }

        // zero fill tail of new_d
        {
            const float4 z = make_float4(0.f, 0.f, 0.f, 0.f);
            float* __restrict__ dst = out + ((size_t)b * M_ + idx) * V_;
            const int rem4 = (M_ - idx) * (V_ / 4);
            for (int i = tid; i < rem4; i += NT)
                ((float4*)dst)[i] = z;
        }
        __syncthreads();   // s_sel reused next batch
    }

    // ---- reset barrier state for the next graph replay ----
    if (tid == 0) {
        const int old = atomicAdd(&g_done, 1);
        if (old == GRID - 1) {
            g_done = 0;
            g_go   = 0;
        }
    }
}

extern "C" void kernel_launch(void* const* d_in, const int* in_sizes, int n_in,
                              void* d_out, int out_size)
{
    (void)in_sizes; (void)n_in; (void)out_size;
    const float* decodings    = (const float*)d_in[0];
    // d_in[1] = variables : unused (new_v is all zeros)
    const int*   target_types = (const int*)d_in[2];
    const int*   spans        = (const int*)d_in[3];
    const float* te_table     = (const float*)d_in[4];
    const float* W_sem        = (const float*)d_in[5];
    const float* b_sem        = (const float*)d_in[6];
    const float* gumbel       = (const float*)d_in[7];
    float*       out          = (float*)d_out;

    persistent_kernel<<<GRID, NT>>>(
        decodings, target_types, spans, te_table, W_sem, b_sem, gumbel, out);
}

// round 6
// speedup vs baseline: 2.8714x; 2.8714x over previous
#include <cuda_runtime.h>
#include <math_constants.h>

// Problem constants (from reference)
#define B_      256
#define N_      16
#define M_      128
#define V_      64
#define H_      256
#define K_      8
#define NP1_    17      // N + 1
#define KO_     136     // K * (N+1)
#define TYPES_  12
#define NTHREADS 512

// Output layout: new_d [B,M,V] floats, then new_v [B,40,3,V] zeros
#define OUT_D_ELEMS ((size_t)B_ * M_ * V_)
#define OUT_V_PER_B (40 * 3 * V_)   // 7680 floats per batch

__global__ __launch_bounds__(NTHREADS, 2)
void fused_dt_apply_kernel(
    const float* __restrict__ decodings,     // [B,N,M,V]
    const int*   __restrict__ target_types,  // [B]
    const int*   __restrict__ spans,         // [B]
    const float* __restrict__ te_table,      // [21,H]
    const float* __restrict__ W_sem,         // [15,12,H,KO]
    const float* __restrict__ b_sem,         // [15,12,KO]
    const float* __restrict__ gumbel,        // [B,K,NP1]
    float*       __restrict__ out)           // [OUT_D | OUT_V]
{
    __shared__ float  s_te[H_];
    __shared__ double s_partd[2 * KO_];
    __shared__ float  s_logit[KO_];
    __shared__ int    s_sel[K_];
    __shared__ int    s_red[16];
    __shared__ int    s_olen;

    const int b    = blockIdx.x;
    const int tid  = threadIdx.x;
    const int w    = tid >> 5;
    const int lane = tid & 31;
    const int tt   = target_types[b];
    const int sp   = spans[b];

    // gumbel prefetch — independent load, flies during the GEMV chain
    float gval = 0.f;
    if (w < K_ && lane < NP1_)
        gval = __ldg(&gumbel[((size_t)b * K_ + w) * NP1_ + lane]);

    // ---------------- Phase 1: selection indices sel[k] in [0,16] ----------------
    if (tt == 20) {
        // fixed start template: k=0 -> decoding 0 (n=1), others -> pad (n=0)
        if (tid < K_) s_sel[tid] = (tid == 0) ? 1 : 0;
        __syncthreads();
    } else {
        if (tid < H_) s_te[tid] = te_table[(size_t)tt * H_ + tid];
        __syncthreads();

        const size_t gidx = (size_t)(sp - 2) * TYPES_ + (size_t)(tt - 9);
        const float* __restrict__ Wg = W_sem + gidx * (size_t)H_ * KO_;
        const float* __restrict__ bg = b_sem + gidx * KO_;

        // 272 threads: (half of H) x (136 outputs). 8 fp32 accumulators each,
        // combined in fp64 (identical numerics to the 16.9us baseline).
        if (tid < 2 * KO_) {
            const int o  = (tid < KO_) ? tid : (tid - KO_);
            const int h0 = (tid < KO_) ? 0 : 128;
            float a0 = 0.f, a1 = 0.f, a2 = 0.f, a3 = 0.f;
            float a4 = 0.f, a5 = 0.f, a6 = 0.f, a7 = 0.f;
            const float* wp = Wg + (size_t)h0 * KO_ + o;
            const float* tp = s_te + h0;
            #pragma unroll 4
            for (int h = 0; h < 128; h += 8) {
                a0 = fmaf(tp[h + 0], wp[(size_t)(h + 0) * KO_], a0);
                a1 = fmaf(tp[h + 1], wp[(size_t)(h + 1) * KO_], a1);
                a2 = fmaf(tp[h + 2], wp[(size_t)(h + 2) * KO_], a2);
                a3 = fmaf(tp[h + 3], wp[(size_t)(h + 3) * KO_], a3);
                a4 = fmaf(tp[h + 4], wp[(size_t)(h + 4) * KO_], a4);
                a5 = fmaf(tp[h + 5], wp[(size_t)(h + 5) * KO_], a5);
                a6 = fmaf(tp[h + 6], wp[(size_t)(h + 6) * KO_], a6);
                a7 = fmaf(tp[h + 7], wp[(size_t)(h + 7) * KO_], a7);
            }
            double sum = (((double)a0 + (double)a1) + ((double)a2 + (double)a3))
                       + (((double)a4 + (double)a5) + ((double)a6 + (double)a7));
            s_partd[tid] = sum;
        }
        __syncthreads();

        if (tid < KO_) {
            s_logit[tid] = (float)(s_partd[tid] + s_partd[tid + KO_]) + bg[tid];
        }
        __syncthreads();

        // argmax over valid n of (logits + gumbel): warp w handles k = w
        if (w < K_) {
            float val = -CUDART_INF_F;
            if (lane < NP1_ && lane <= sp)
                val = s_logit[w * NP1_ + lane] + gval;
            float bv = val;
            int   bn = lane;
            #pragma unroll
            for (int off = 16; off; off >>= 1) {
                float ov = __shfl_down_sync(0xffffffffu, bv, off);
                int   on = __shfl_down_sync(0xffffffffu, bn, off);
                if (ov > bv || (ov == bv && on < bn)) { bv = ov; bn = on; }
            }
            if (lane == 0) s_sel[w] = bn;
        }
        __syncthreads();
    }

    // ---------------- Phase 2: fused speculative copy + olen ----------------
    // Copy all 128 rows of the selected tile while computing olen from the
    // same registers; rows beyond olen are overwritten by the next segment or
    // the zero fill (idx strictly increases -> exact semantics).
    const int c4    = tid & 15;    // float4 column within row (V=64 -> 16 float4)
    const int rbase = tid >> 4;    // base row 0..31
    int idx = 0;

    for (int k = 0; k < K_; k++) {
        if (idx >= M_) break;
        const int n = s_sel[k];
        if (n == 0) continue;

        const float4* __restrict__ tile4 =
            (const float4*)(decodings + ((size_t)b * N_ + (size_t)(n - 1)) * (M_ * V_));
        float4* __restrict__ out4 =
            (float4*)(out + ((size_t)b * M_ + idx) * V_);

        float4 v[4];
        #pragma unroll
        for (int j = 0; j < 4; j++)
            v[j] = tile4[(rbase + 32 * j) * 16 + c4];

        int local = 0;
        #pragma unroll
        for (int j = 0; j < 4; j++) {
            const int row = rbase + 32 * j;
            if (idx + row < M_)
                out4[row * 16 + c4] = v[j];
            // row non-pad iff max over v>0 of d[row][v] > d[row][0]
            float m = (c4 == 0) ? fmaxf(fmaxf(v[j].y, v[j].z), v[j].w)
                                : fmaxf(fmaxf(v[j].x, v[j].y), fmaxf(v[j].z, v[j].w));
            #pragma unroll
            for (int off = 1; off < 16; off <<= 1)
                m = fmaxf(m, __shfl_xor_sync(0xffffffffu, m, off));
            const float d0 = __shfl_sync(0xffffffffu, v[j].x, lane & 16);
            if (m > d0) local = row + 1;
        }
        #pragma unroll
        for (int off = 16; off; off >>= 1)
            local = max(local, __shfl_down_sync(0xffffffffu, local, off));
        if (lane == 0) s_red[w] = local;
        __syncthreads();
        if (tid == 0) {
            int o = 0;
            #pragma unroll
            for (int i = 0; i < 16; i++) o = max(o, s_red[i]);
            s_olen = o;
        }
        __syncthreads();
        idx += min(s_olen, M_ - idx);
    }

    // ---------------- Phase 3: zero fill (tail of new_d, all of new_v) ----------------
    const float4 z = make_float4(0.f, 0.f, 0.f, 0.f);
    {
        float* __restrict__ dst = out + ((size_t)b * M_ + idx) * V_;
        const int rem4 = (M_ - idx) * (V_ / 4);
        for (int i = tid; i < rem4; i += NTHREADS)
            ((float4*)dst)[i] = z;
    }
    {
        float* __restrict__ dv = out + OUT_D_ELEMS + (size_t)b * OUT_V_PER_B;
        #pragma unroll
        for (int i = tid; i < OUT_V_PER_B / 4; i += NTHREADS)
            ((float4*)dv)[i] = z;
    }
}

extern "C" void kernel_launch(void* const* d_in, const int* in_sizes, int n_in,
                              void* d_out, int out_size)
{
    (void)in_sizes; (void)n_in; (void)out_size;
    const float* decodings    = (const float*)d_in[0];
    // d_in[1] = variables : unused (new_v is all zeros)
    const int*   target_types = (const int*)d_in[2];
    const int*   spans        = (const int*)d_in[3];
    const float* te_table     = (const float*)d_in[4];
    const float* W_sem        = (const float*)d_in[5];
    const float* b_sem        = (const float*)d_in[6];
    const float* gumbel       = (const float*)d_in[7];
    float*       out          = (float*)d_out;

    fused_dt_apply_kernel<<<B_, NTHREADS>>>(
        decodings, target_types, spans, te_table, W_sem, b_sem, gumbel, out);
}